// round 3
// baseline (speedup 1.0000x reference)
#include <cuda_runtime.h>
#include <cstdint>

#define LL    320
#define DD    128
#define NBINS 32
#define EPSF  1e-8f

#define Z_ELEMS (LL*LL*DD)     // 13,107,200
#define P_ELEMS (3*LL*LL)      //    307,200
// output layout: [z | pxyz | cadistavg], all f32

// ---- cadistavg: 32x32 output tiles, upper triangle only (symmetric)
#define NT2 10                  // 320/32
#define C_BLOCKS 55             // NT2*(NT2+1)/2
#define CH 8                    // i-chunk depth staged in smem
// ---- z path
#define Z_BLOCKS (LL*LL/8)      // 12800: 8 pairs/block, 32 lanes x float4 over D=128
// ---- pxyz path
#define P_BLOCKS (P_ELEMS/4/256) // 300

__device__ __forceinline__ float fsqrt_approx(float x) {
    float y;
    asm("sqrt.approx.f32 %0, %1;" : "=f"(y) : "f"(x));
    return y;
}

__device__ __forceinline__ float dist3(float4 a, float4 b) {
    float dx = a.x - b.x, dy = a.y - b.y, dz = a.z - b.z;
    return fsqrt_approx(fmaf(dx, dx, fmaf(dy, dy, fmaf(dz, dz, EPSF))));
}

__global__ __launch_bounds__(256)
void spired_fused(const int* __restrict__ residx,
                  const int* __restrict__ mask,        // bool delivered as int32
                  const float* __restrict__ emb,
                  const float4* __restrict__ pair4,
                  const float* __restrict__ predxyz,
                  const float* __restrict__ maskdiag,
                  float* __restrict__ out)
{
    const int blk = blockIdx.x;
    const int tid = threadIdx.x;

    if (blk < C_BLOCKS) {
        // cadistavg[j,k] = (1/L) sum_i sqrt(sum_c (px[c,i,k]-px[c,i,j])^2 + eps)
        // Upper-triangle 32x32 tiles; each thread computes a 2x2 register block.
        __shared__ float4 sK[CH][32];
        __shared__ float4 sJ[CH][32];

        // map blk -> (a,b) with a<=b over NT2 tiles
        int a = 0, t = blk;
        while (t >= NT2 - a) { t -= NT2 - a; a++; }
        const int b2 = a + t;
        const int jt = a * 32;
        const int kt = b2 * 32;

        const int tx = tid & 15;     // k sub-col (and +16)
        const int ty = tid >> 4;     // j sub-row (and +16)
        const int ii_s = tid >> 5;   // staging: i within chunk (0..7)
        const int kk_s = tid & 31;   // staging: col within tile

        float acc00 = 0.f, acc01 = 0.f, acc10 = 0.f, acc11 = 0.f;

        for (int i0 = 0; i0 < LL; i0 += CH) {
            const int gi = i0 + ii_s;
            {
                int col = kt + kk_s;
                float md = maskdiag[gi * LL + col];
                float x = predxyz[0 * LL * LL + gi * LL + col] * md;
                float y = predxyz[1 * LL * LL + gi * LL + col] * md;
                float z = predxyz[2 * LL * LL + gi * LL + col] * md;
                sK[ii_s][kk_s] = make_float4(x, y, z, 0.f);
                col = jt + kk_s;
                md = maskdiag[gi * LL + col];
                x = predxyz[0 * LL * LL + gi * LL + col] * md;
                y = predxyz[1 * LL * LL + gi * LL + col] * md;
                z = predxyz[2 * LL * LL + gi * LL + col] * md;
                sJ[ii_s][kk_s] = make_float4(x, y, z, 0.f);
            }
            __syncthreads();
            #pragma unroll
            for (int ii = 0; ii < CH; ii++) {
                float4 ka = sK[ii][tx];
                float4 kb = sK[ii][tx + 16];
                float4 ja = sJ[ii][ty];
                float4 jb = sJ[ii][ty + 16];
                acc00 += dist3(ka, ja);
                acc01 += dist3(kb, ja);
                acc10 += dist3(ka, jb);
                acc11 += dist3(kb, jb);
            }
            __syncthreads();
        }

        float* cd = out + Z_ELEMS + P_ELEMS;
        const float s = 1.0f / LL;
        cd[(jt + ty)      * LL + kt + tx]      = acc00 * s;
        cd[(jt + ty)      * LL + kt + tx + 16] = acc01 * s;
        cd[(jt + ty + 16) * LL + kt + tx]      = acc10 * s;
        cd[(jt + ty + 16) * LL + kt + tx + 16] = acc11 * s;
        if (a != b2) {  // mirror into lower triangle
            cd[(kt + tx)      * LL + jt + ty]      = acc00 * s;
            cd[(kt + tx + 16) * LL + jt + ty]      = acc01 * s;
            cd[(kt + tx)      * LL + jt + ty + 16] = acc10 * s;
            cd[(kt + tx + 16) * LL + jt + ty + 16] = acc11 * s;
        }

    } else if (blk < C_BLOCKS + Z_BLOCKS) {
        // ---- z = pair_feats + emb_table[idx(i,j)]
        const int b    = blk - C_BLOCKS;
        const int lane = tid & 31;             // float4 slot over D=128
        const int p    = b * 8 + (tid >> 5);   // pair index (i*L + j)
        const int i    = p / LL;
        const int j    = p - i * LL;

        int m   = mask[i] & mask[j];
        int dif = residx[j] - residx[i];
        dif = min(max(dif, -NBINS), NBINS) + (NBINS + 1);
        const int idx = m ? dif : 0;

        const float4* e4 = (const float4*)emb;
        float4 ev = e4[idx * (DD / 4) + lane];
        float4 pv = pair4[(size_t)p * (DD / 4) + lane];
        float4 z  = make_float4(pv.x + ev.x, pv.y + ev.y, pv.z + ev.z, pv.w + ev.w);
        ((float4*)out)[(size_t)p * (DD / 4) + lane] = z;

    } else {
        // ---- pxyz = predxyz * maskdiag  (maskdiag broadcast over c)
        const int b = blk - C_BLOCKS - Z_BLOCKS;
        const int e = b * 256 + tid;           // float4 index, < 76800
        const float4* pr4 = (const float4*)predxyz;
        const float4* md4 = (const float4*)maskdiag;
        float4 pv = pr4[e];
        float4 mv = md4[e % (LL * LL / 4)];
        float4 r  = make_float4(pv.x * mv.x, pv.y * mv.y, pv.z * mv.z, pv.w * mv.w);
        ((float4*)(out + Z_ELEMS))[e] = r;
    }
}

extern "C" void kernel_launch(void* const* d_in, const int* in_sizes, int n_in,
                              void* d_out, int out_size) {
    const int*    residx   = (const int*)d_in[0];
    const int*    mask     = (const int*)d_in[1];
    const float*  emb      = (const float*)d_in[2];
    const float4* pair4    = (const float4*)d_in[3];
    const float*  predxyz  = (const float*)d_in[4];
    const float*  maskdiag = (const float*)d_in[5];
    float*        out      = (float*)d_out;

    const int grid = C_BLOCKS + Z_BLOCKS + P_BLOCKS;  // 13155
    spired_fused<<<grid, 256>>>(residx, mask, emb, pair4, predxyz, maskdiag, out);
}

// round 4
// speedup vs baseline: 1.4707x; 1.4707x over previous
#include <cuda_runtime.h>
#include <cstdint>

#define LL    320
#define DD    128
#define NBINS 32
#define EPSF  1e-8f

#define Z_ELEMS (LL*LL*DD)     // 13,107,200
#define P_ELEMS (3*LL*LL)      //    307,200
// output layout: [z | pxyz | cadistavg], all f32

// ---- cadistavg: 16x16 tiles, upper triangle (symmetric), 210 blocks
#define NT 20                   // 320/16
#define C_BLOCKS 210            // NT*(NT+1)/2
#define CH 16                   // i-chunk depth staged in smem
// ---- z: 8 warps/block, each warp does 8 pairs -> 64 pairs/block
#define ZP_PER_BLOCK 64
#define Z_BLOCKS (LL*LL/ZP_PER_BLOCK)   // 1600
// ---- pxyz
#define P_BLOCKS (P_ELEMS/4/256)        // 300

__device__ __forceinline__ float fsqrt_approx(float x) {
    float y;
    asm("sqrt.approx.f32 %0, %1;" : "=f"(y) : "f"(x));
    return y;
}

__device__ __forceinline__ float dist3(float4 a, float4 b) {
    float dx = a.x - b.x, dy = a.y - b.y, dz = a.z - b.z;
    return fsqrt_approx(fmaf(dx, dx, fmaf(dy, dy, fmaf(dz, dz, EPSF))));
}

__global__ __launch_bounds__(256)
void spired_fused(const int* __restrict__ residx,
                  const int* __restrict__ mask,        // bool delivered as int32
                  const float* __restrict__ emb,
                  const float4* __restrict__ pair4,
                  const float* __restrict__ predxyz,
                  const float* __restrict__ maskdiag,
                  float* __restrict__ out)
{
    const int blk = blockIdx.x;
    const int tid = threadIdx.x;

    if (blk < C_BLOCKS) {
        // cadistavg[j,k] = (1/L) sum_i sqrt(sum_c (px[c,i,k]-px[c,i,j])^2 + eps)
        // 16x16 tile per block, one output per thread, upper triangle + mirror.
        __shared__ float4 sK[CH][16];
        __shared__ float4 sJ[CH][16];

        // blk -> (a, b2) with a <= b2 over NT row/col tiles
        int a = 0, t = blk;
        while (t >= NT - a) { t -= NT - a; a++; }
        const int b2 = a + t;
        const int jt = a * 16;
        const int kt = b2 * 16;

        const int tx = tid & 15;    // k within tile (also staging col)
        const int ty = tid >> 4;    // j within tile (also staging i-row)

        float acc0 = 0.f, acc1 = 0.f, acc2 = 0.f, acc3 = 0.f;

        for (int i0 = 0; i0 < LL; i0 += CH) {
            const int gi = i0 + ty;          // staging i-row
            {
                int col = kt + tx;
                float md = maskdiag[gi * LL + col];
                sK[ty][tx] = make_float4(
                    predxyz[0 * LL * LL + gi * LL + col] * md,
                    predxyz[1 * LL * LL + gi * LL + col] * md,
                    predxyz[2 * LL * LL + gi * LL + col] * md, 0.f);
                col = jt + tx;
                md = maskdiag[gi * LL + col];
                sJ[ty][tx] = make_float4(
                    predxyz[0 * LL * LL + gi * LL + col] * md,
                    predxyz[1 * LL * LL + gi * LL + col] * md,
                    predxyz[2 * LL * LL + gi * LL + col] * md, 0.f);
            }
            __syncthreads();
            #pragma unroll
            for (int ii = 0; ii < CH; ii += 4) {
                acc0 += dist3(sK[ii + 0][tx], sJ[ii + 0][ty]);
                acc1 += dist3(sK[ii + 1][tx], sJ[ii + 1][ty]);
                acc2 += dist3(sK[ii + 2][tx], sJ[ii + 2][ty]);
                acc3 += dist3(sK[ii + 3][tx], sJ[ii + 3][ty]);
            }
            __syncthreads();
        }

        float* cd = out + Z_ELEMS + P_ELEMS;
        const float v = (acc0 + acc1 + acc2 + acc3) * (1.0f / LL);
        cd[(jt + ty) * LL + (kt + tx)] = v;
        if (a != b2)
            cd[(kt + tx) * LL + (jt + ty)] = v;       // symmetric mirror

    } else if (blk < C_BLOCKS + Z_BLOCKS) {
        // ---- z = pair_feats + emb_table[idx(i,j)]; 8 pairs per warp (MLP)
        const int b    = blk - C_BLOCKS;
        const int lane = tid & 31;                    // float4 slot over D=128
        const int base = b * ZP_PER_BLOCK + (tid >> 5) * 8;
        const float4* e4 = (const float4*)emb;

        #pragma unroll
        for (int u = 0; u < 8; u++) {
            const int p = base + u;
            const int i = p / LL;
            const int j = p - i * LL;
            int m   = mask[i] & mask[j];
            int dif = residx[j] - residx[i];
            dif = min(max(dif, -NBINS), NBINS) + (NBINS + 1);
            const int idx = m ? dif : 0;

            float4 ev = e4[idx * (DD / 4) + lane];
            float4 pv = pair4[(size_t)p * (DD / 4) + lane];
            float4 z  = make_float4(pv.x + ev.x, pv.y + ev.y,
                                    pv.z + ev.z, pv.w + ev.w);
            ((float4*)out)[(size_t)p * (DD / 4) + lane] = z;
        }

    } else {
        // ---- pxyz = predxyz * maskdiag  (maskdiag broadcast over c)
        const int b = blk - C_BLOCKS - Z_BLOCKS;
        const int e = b * 256 + tid;           // float4 index, < 76800
        const float4* pr4 = (const float4*)predxyz;
        const float4* md4 = (const float4*)maskdiag;
        float4 pv = pr4[e];
        float4 mv = md4[e % (LL * LL / 4)];
        float4 r  = make_float4(pv.x * mv.x, pv.y * mv.y, pv.z * mv.z, pv.w * mv.w);
        ((float4*)(out + Z_ELEMS))[e] = r;
    }
}

extern "C" void kernel_launch(void* const* d_in, const int* in_sizes, int n_in,
                              void* d_out, int out_size) {
    const int*    residx   = (const int*)d_in[0];
    const int*    mask     = (const int*)d_in[1];
    const float*  emb      = (const float*)d_in[2];
    const float4* pair4    = (const float4*)d_in[3];
    const float*  predxyz  = (const float*)d_in[4];
    const float*  maskdiag = (const float*)d_in[5];
    float*        out      = (float*)d_out;

    const int grid = C_BLOCKS + Z_BLOCKS + P_BLOCKS;  // 2110
    spired_fused<<<grid, 256>>>(residx, mask, emb, pair4, predxyz, maskdiag, out);
}

// round 5
// speedup vs baseline: 1.4814x; 1.0073x over previous
#include <cuda_runtime.h>
#include <cstdint>

#define LL    320
#define DD    128
#define NBINS 32
#define EPSF  1e-8f

#define Z_ELEMS (LL*LL*DD)     // 13,107,200
#define P_ELEMS (3*LL*LL)      //    307,200
// output layout: [z | pxyz | cadistavg], all f32

// ---- cadistavg: 16x16 tiles, upper triangle (symmetric), 210 blocks
#define NT 20                   // 320/16
#define C_BLOCKS 210            // NT*(NT+1)/2
#define CH 16                   // i-chunk depth staged in smem
// ---- z: 8 warps/block, each warp does 8 pairs -> 64 pairs/block
#define ZP_PER_BLOCK 64
#define Z_BLOCKS (LL*LL/ZP_PER_BLOCK)   // 1600
// ---- pxyz
#define P_BLOCKS (P_ELEMS/4/256)        // 300

__device__ __forceinline__ float fsqrt_approx(float x) {
    float y;
    asm("sqrt.approx.f32 %0, %1;" : "=f"(y) : "f"(x));
    return y;
}

__device__ __forceinline__ float dist3(float4 a, float4 b) {
    float dx = a.x - b.x, dy = a.y - b.y, dz = a.z - b.z;
    return fsqrt_approx(fmaf(dx, dx, fmaf(dy, dy, fmaf(dz, dz, EPSF))));
}

__global__ __launch_bounds__(256)
void spired_fused(const int* __restrict__ residx,
                  const int* __restrict__ mask,        // bool delivered as int32
                  const float* __restrict__ emb,
                  const float4* __restrict__ pair4,
                  const float* __restrict__ predxyz,
                  const float* __restrict__ maskdiag,
                  float* __restrict__ out)
{
    const int blk = blockIdx.x;
    const int tid = threadIdx.x;

    if (blk < C_BLOCKS) {
        // cadistavg[j,k] = (1/L) sum_i sqrt(sum_c (px[c,i,k]-px[c,i,j])^2 + eps)
        // 16x16 tile per block, one output per thread, upper triangle + mirror.
        __shared__ float4 sK[CH][16];
        __shared__ float4 sJ[CH][16];

        // blk -> (a, b2) with a <= b2 over NT row/col tiles
        int a = 0, t = blk;
        while (t >= NT - a) { t -= NT - a; a++; }
        const int b2 = a + t;
        const int jt = a * 16;
        const int kt = b2 * 16;

        const int tx = tid & 15;    // k within tile (also staging col)
        const int ty = tid >> 4;    // j within tile (also staging i-row)

        float acc0 = 0.f, acc1 = 0.f, acc2 = 0.f, acc3 = 0.f;

        for (int i0 = 0; i0 < LL; i0 += CH) {
            const int gi = i0 + ty;          // staging i-row
            {
                int col = kt + tx;
                float md = maskdiag[gi * LL + col];
                sK[ty][tx] = make_float4(
                    predxyz[0 * LL * LL + gi * LL + col] * md,
                    predxyz[1 * LL * LL + gi * LL + col] * md,
                    predxyz[2 * LL * LL + gi * LL + col] * md, 0.f);
                col = jt + tx;
                md = maskdiag[gi * LL + col];
                sJ[ty][tx] = make_float4(
                    predxyz[0 * LL * LL + gi * LL + col] * md,
                    predxyz[1 * LL * LL + gi * LL + col] * md,
                    predxyz[2 * LL * LL + gi * LL + col] * md, 0.f);
            }
            __syncthreads();
            #pragma unroll
            for (int ii = 0; ii < CH; ii += 4) {
                acc0 += dist3(sK[ii + 0][tx], sJ[ii + 0][ty]);
                acc1 += dist3(sK[ii + 1][tx], sJ[ii + 1][ty]);
                acc2 += dist3(sK[ii + 2][tx], sJ[ii + 2][ty]);
                acc3 += dist3(sK[ii + 3][tx], sJ[ii + 3][ty]);
            }
            __syncthreads();
        }

        float* cd = out + Z_ELEMS + P_ELEMS;
        const float v = (acc0 + acc1 + acc2 + acc3) * (1.0f / LL);
        cd[(jt + ty) * LL + (kt + tx)] = v;
        if (a != b2)
            cd[(kt + tx) * LL + (jt + ty)] = v;       // symmetric mirror

    } else if (blk < C_BLOCKS + Z_BLOCKS) {
        // ---- z = pair_feats + emb_table[idx(i,j)]
        // 8 pairs per warp; all 16 LDG.128 issued before any consumption (MLP).
        const int b    = blk - C_BLOCKS;
        const int lane = tid & 31;                    // float4 slot over D=128
        const int base = b * ZP_PER_BLOCK + (tid >> 5) * 8;
        const int i    = base / LL;                   // same row for all 8 pairs
        const int j0   = base - i * LL;
        const float4* e4 = (const float4*)emb;

        const int   mi = mask[i];
        const int   ri = residx[i];

        int idx[8];
        #pragma unroll
        for (int u = 0; u < 8; u++) {
            const int j = j0 + u;
            int m   = mi & mask[j];
            int dif = residx[j] - ri;
            dif = min(max(dif, -NBINS), NBINS) + (NBINS + 1);
            idx[u] = m ? dif : 0;
        }

        float4 pv[8], ev[8];
        #pragma unroll
        for (int u = 0; u < 8; u++)
            pv[u] = pair4[(size_t)(base + u) * (DD / 4) + lane];
        #pragma unroll
        for (int u = 0; u < 8; u++)
            ev[u] = e4[idx[u] * (DD / 4) + lane];

        #pragma unroll
        for (int u = 0; u < 8; u++) {
            float4 z = make_float4(pv[u].x + ev[u].x, pv[u].y + ev[u].y,
                                   pv[u].z + ev[u].z, pv[u].w + ev[u].w);
            ((float4*)out)[(size_t)(base + u) * (DD / 4) + lane] = z;
        }

    } else {
        // ---- pxyz = predxyz * maskdiag  (maskdiag broadcast over c)
        const int b = blk - C_BLOCKS - Z_BLOCKS;
        const int e = b * 256 + tid;           // float4 index, < 76800
        const float4* pr4 = (const float4*)predxyz;
        const float4* md4 = (const float4*)maskdiag;
        float4 pv = pr4[e];
        float4 mv = md4[e % (LL * LL / 4)];
        float4 r  = make_float4(pv.x * mv.x, pv.y * mv.y, pv.z * mv.z, pv.w * mv.w);
        ((float4*)(out + Z_ELEMS))[e] = r;
    }
}

extern "C" void kernel_launch(void* const* d_in, const int* in_sizes, int n_in,
                              void* d_out, int out_size) {
    const int*    residx   = (const int*)d_in[0];
    const int*    mask     = (const int*)d_in[1];
    const float*  emb      = (const float*)d_in[2];
    const float4* pair4    = (const float4*)d_in[3];
    const float*  predxyz  = (const float*)d_in[4];
    const float*  maskdiag = (const float*)d_in[5];
    float*        out      = (float*)d_out;

    const int grid = C_BLOCKS + Z_BLOCKS + P_BLOCKS;  // 2110
    spired_fused<<<grid, 256>>>(residx, mask, emb, pair4, predxyz, maskdiag, out);
}